// round 1
// baseline (speedup 1.0000x reference)
#include <cuda_runtime.h>
#include <math.h>

// Problem constants
#define NN 256
#define TT 128
#define DD 512
#define HH 1024
#define GG 4096   // 4*H
#define LL 16     // 4x4 spatial locations

// ---------------- scratch (device globals; no cudaMalloc allowed) ----------------
__device__ float g_h[NN * HH];
__device__ float g_c[NN * HH];
__device__ float g_w[NN * LL];
__device__ float g_gates[NN * GG];
__device__ float g_AW[(size_t)NN * LL * GG];   // 67 MB: AW[n,l,j] = sum_h A[n,h,l]*Wattn[h,j]

// ---------------- init: h0 = c0 = mean_l A[n,h,l] ----------------
__global__ void k_init(const float* __restrict__ A)
{
    int idx = blockIdx.x * blockDim.x + threadIdx.x;  // over NN*HH
    if (idx >= NN * HH) return;
    const float4* p = (const float4*)(A + (size_t)idx * LL);
    float4 a0 = p[0], a1 = p[1], a2 = p[2], a3 = p[3];
    float s = a0.x + a0.y + a0.z + a0.w
            + a1.x + a1.y + a1.z + a1.w
            + a2.x + a2.y + a2.z + a2.w
            + a3.x + a3.y + a3.z + a3.w;
    s *= (1.0f / LL);
    g_h[idx] = s;
    g_c[idx] = s;
}

// ---------------- AW precompute: AW[(n,l), j] = sum_h A[n,h,l] * Wattn[h,j] ----------------
// Tiled SGEMM: M = NN*LL = 4096 (m = n*16+l), K = HH, N = GG.
// Block tile 64x128, bk=16, 128 threads, 8x8 per-thread microtile.
__global__ __launch_bounds__(128) void k_aw(const float* __restrict__ A,
                                            const float* __restrict__ Wattn)
{
    __shared__ float As[16][64];
    __shared__ float Bs[16][128];
    int tid = threadIdx.x;
    int m0 = blockIdx.y * 64;
    int j0 = blockIdx.x * 128;
    int tx = tid & 15;        // 0..15 -> 8 cols each
    int ty = tid >> 4;        // 0..7  -> 8 rows each

    float acc[8][8];
#pragma unroll
    for (int r = 0; r < 8; r++)
#pragma unroll
        for (int c = 0; c < 8; c++) acc[r][c] = 0.0f;

    for (int k0 = 0; k0 < HH; k0 += 16) {
        // As: 64 m x 16 k (1024 floats, 8 per thread), stored [k][m]
#pragma unroll
        for (int i = 0; i < 8; i++) {
            int e  = tid + i * 128;       // 0..1023
            int mm = e & 63;
            int kk = e >> 6;
            int m  = m0 + mm;
            int n  = m >> 4;
            int l  = m & 15;
            As[kk][mm] = A[(size_t)n * (HH * LL) + (size_t)(k0 + kk) * LL + l];
        }
        // Bs: 16 k x 128 j (512 float4, 4 per thread)
#pragma unroll
        for (int i = 0; i < 4; i++) {
            int e  = tid + i * 128;       // 0..511
            int kk = e >> 5;
            int j4 = e & 31;
            *(float4*)&Bs[kk][j4 * 4] =
                *(const float4*)&Wattn[(size_t)(k0 + kk) * GG + j0 + j4 * 4];
        }
        __syncthreads();
#pragma unroll
        for (int kk = 0; kk < 16; kk++) {
            float4 a0 = *(float4*)&As[kk][ty * 8];
            float4 a1 = *(float4*)&As[kk][ty * 8 + 4];
            float4 b0 = *(float4*)&Bs[kk][tx * 8];
            float4 b1 = *(float4*)&Bs[kk][tx * 8 + 4];
            float av[8] = {a0.x, a0.y, a0.z, a0.w, a1.x, a1.y, a1.z, a1.w};
            float bv[8] = {b0.x, b0.y, b0.z, b0.w, b1.x, b1.y, b1.z, b1.w};
#pragma unroll
            for (int r = 0; r < 8; r++)
#pragma unroll
                for (int c = 0; c < 8; c++) acc[r][c] += av[r] * bv[c];
        }
        __syncthreads();
    }
#pragma unroll
    for (int r = 0; r < 8; r++) {
        int m = m0 + ty * 8 + r;
        float4* dst = (float4*)&g_AW[(size_t)m * GG + j0 + tx * 8];
        dst[0] = make_float4(acc[r][0], acc[r][1], acc[r][2], acc[r][3]);
        dst[1] = make_float4(acc[r][4], acc[r][5], acc[r][6], acc[r][7]);
    }
}

// ---------------- per-step attention weights: w[n,:] = softmax(scale * A[n]^T h[n]) ----------------
__global__ void k_attn(const float* __restrict__ A)
{
    int n   = blockIdx.x;
    int tid = threadIdx.x;  // 256 threads
    __shared__ float sh[HH];
    __shared__ float red[8][16];
    __shared__ float swv[16];

    for (int i = tid; i < HH; i += 256) sh[i] = g_h[n * HH + i];
    __syncthreads();

    float acc[16];
#pragma unroll
    for (int l = 0; l < 16; l++) acc[l] = 0.0f;

    for (int hh = tid; hh < HH; hh += 256) {
        float hv = sh[hh];
        const float4* ap = (const float4*)&A[((size_t)n * HH + hh) * LL];
        float4 a0 = ap[0], a1 = ap[1], a2 = ap[2], a3 = ap[3];
        acc[0]  += a0.x * hv; acc[1]  += a0.y * hv; acc[2]  += a0.z * hv; acc[3]  += a0.w * hv;
        acc[4]  += a1.x * hv; acc[5]  += a1.y * hv; acc[6]  += a1.z * hv; acc[7]  += a1.w * hv;
        acc[8]  += a2.x * hv; acc[9]  += a2.y * hv; acc[10] += a2.z * hv; acc[11] += a2.w * hv;
        acc[12] += a3.x * hv; acc[13] += a3.y * hv; acc[14] += a3.z * hv; acc[15] += a3.w * hv;
    }
    // intra-warp reduce (all lanes end up with warp sums)
#pragma unroll
    for (int off = 16; off; off >>= 1)
#pragma unroll
        for (int l = 0; l < 16; l++)
            acc[l] += __shfl_xor_sync(0xffffffff, acc[l], off);

    int wid = tid >> 5, lane = tid & 31;
    if (lane < 16) red[wid][lane] = acc[lane];
    __syncthreads();

    if (tid < 16) {
        float s = 0.0f;
#pragma unroll
        for (int wq = 0; wq < 8; wq++) s += red[wq][tid];
        swv[tid] = s * 0.03125f;  // 1/sqrt(1024)
    }
    __syncthreads();

    if (tid == 0) {
        float mx = swv[0];
#pragma unroll
        for (int l = 1; l < 16; l++) mx = fmaxf(mx, swv[l]);
        float e[16], den = 0.0f;
#pragma unroll
        for (int l = 0; l < 16; l++) { e[l] = expf(swv[l] - mx); den += e[l]; }
        float inv = 1.0f / den;
#pragma unroll
        for (int l = 0; l < 16; l++) g_w[n * LL + l] = e[l] * inv;
    }
}

// ---------------- per-step fused GEMM: gates = [x_t | h] @ [Wx; Wh] + b + sum_l w*AW ----------------
// M = 256 (n), K = D+H = 1536, N = 4096. Block tile 64x128, bk=16, 128 threads, 8x8 microtile.
__global__ __launch_bounds__(128) void k_gemm(const float* __restrict__ x,
                                              const float* __restrict__ Wx,
                                              const float* __restrict__ Wh,
                                              const float* __restrict__ b,
                                              int t)
{
    __shared__ float As[16][64];
    __shared__ float Bs[16][128];
    __shared__ float sw[64][16];
    int tid = threadIdx.x;
    int n0  = blockIdx.y * 64;
    int j0  = blockIdx.x * 128;
    int tx  = tid & 15;
    int ty  = tid >> 4;

    // preload attention weights for this block's 64 rows (1024 floats, 8/thread)
#pragma unroll
    for (int i = 0; i < 8; i++) {
        int e = tid + i * 128;
        sw[e >> 4][e & 15] = g_w[(n0 + (e >> 4)) * LL + (e & 15)];
    }

    float acc[8][8];
#pragma unroll
    for (int r = 0; r < 8; r++)
#pragma unroll
        for (int c = 0; c < 8; c++) acc[r][c] = 0.0f;

    const int K = DD + HH;  // 1536; DD % 16 == 0 so each bk-tile lives wholly in x or h
    for (int k0 = 0; k0 < K; k0 += 16) {
        // As: 64 rows x 16 k -> 256 float4, 2 per thread; store transposed [k][m]
#pragma unroll
        for (int i = 0; i < 2; i++) {
            int f4  = tid * 2 + i;     // 0..255
            int row = f4 >> 2;
            int kq  = f4 & 3;
            int n   = n0 + row;
            int k   = k0 + kq * 4;
            float4 v;
            if (k < DD) v = *(const float4*)&x[(size_t)n * (TT * DD) + (size_t)t * DD + k];
            else        v = *(const float4*)&g_h[(size_t)n * HH + (k - DD)];
            As[kq * 4 + 0][row] = v.x;
            As[kq * 4 + 1][row] = v.y;
            As[kq * 4 + 2][row] = v.z;
            As[kq * 4 + 3][row] = v.w;
        }
        // Bs: 16 k x 128 j
#pragma unroll
        for (int i = 0; i < 4; i++) {
            int e  = tid + i * 128;
            int kk = e >> 5;
            int j4 = e & 31;
            int k  = k0 + kk;
            const float* Bp = (k < DD) ? &Wx[(size_t)k * GG] : &Wh[(size_t)(k - DD) * GG];
            *(float4*)&Bs[kk][j4 * 4] = *(const float4*)&Bp[j0 + j4 * 4];
        }
        __syncthreads();
#pragma unroll
        for (int kk = 0; kk < 16; kk++) {
            float4 a0 = *(float4*)&As[kk][ty * 8];
            float4 a1 = *(float4*)&As[kk][ty * 8 + 4];
            float4 b0 = *(float4*)&Bs[kk][tx * 8];
            float4 b1 = *(float4*)&Bs[kk][tx * 8 + 4];
            float av[8] = {a0.x, a0.y, a0.z, a0.w, a1.x, a1.y, a1.z, a1.w};
            float bv[8] = {b0.x, b0.y, b0.z, b0.w, b1.x, b1.y, b1.z, b1.w};
#pragma unroll
            for (int r = 0; r < 8; r++)
#pragma unroll
                for (int c = 0; c < 8; c++) acc[r][c] += av[r] * bv[c];
        }
        __syncthreads();
    }

    // epilogue: + b[j] + sum_l w[n,l] * AW[n,l,j]; write gates
    int j = j0 + tx * 8;
    float4 bia0 = *(const float4*)&b[j];
    float4 bia1 = *(const float4*)&b[j + 4];
#pragma unroll
    for (int r = 0; r < 8; r++) {
        int rr = ty * 8 + r;
        int n  = n0 + rr;
        float o0 = acc[r][0] + bia0.x, o1 = acc[r][1] + bia0.y;
        float o2 = acc[r][2] + bia0.z, o3 = acc[r][3] + bia0.w;
        float o4 = acc[r][4] + bia1.x, o5 = acc[r][5] + bia1.y;
        float o6 = acc[r][6] + bia1.z, o7 = acc[r][7] + bia1.w;
        const float* awbase = &g_AW[(size_t)n * LL * GG + j];
#pragma unroll
        for (int l = 0; l < 16; l++) {
            float wv = sw[rr][l];
            const float4* aw = (const float4*)(awbase + (size_t)l * GG);
            float4 w0 = aw[0], w1 = aw[1];
            o0 += wv * w0.x; o1 += wv * w0.y; o2 += wv * w0.z; o3 += wv * w0.w;
            o4 += wv * w1.x; o5 += wv * w1.y; o6 += wv * w1.z; o7 += wv * w1.w;
        }
        float4* dst = (float4*)&g_gates[(size_t)n * GG + j];
        dst[0] = make_float4(o0, o1, o2, o3);
        dst[1] = make_float4(o4, o5, o6, o7);
    }
}

// ---------------- per-step pointwise LSTM update ----------------
__global__ void k_point(float* __restrict__ out, int t)
{
    int idx = blockIdx.x * blockDim.x + threadIdx.x;  // NN*HH
    if (idx >= NN * HH) return;
    int n = idx >> 10;
    int p = idx & 1023;
    const float* gb = &g_gates[(size_t)n * GG];
    float iv = gb[p];
    float fv = gb[HH + p];
    float ov = gb[2 * HH + p];
    float gv = gb[3 * HH + p];
    float c  = g_c[idx];
    float si = 1.0f / (1.0f + expf(-iv));
    float sf = 1.0f / (1.0f + expf(-fv));
    float so = 1.0f / (1.0f + expf(-ov));
    float tg = tanhf(gv);
    float cn = sf * c + si * tg;
    float hn = so * tanhf(cn);
    g_c[idx] = cn;
    g_h[idx] = hn;
    out[((size_t)n * TT + t) * HH + p] = hn;
}

// ---------------- launch ----------------
extern "C" void kernel_launch(void* const* d_in, const int* in_sizes, int n_in,
                              void* d_out, int out_size)
{
    const float* x     = (const float*)d_in[0];
    const float* A     = (const float*)d_in[1];
    const float* Wx    = (const float*)d_in[2];
    const float* Wh    = (const float*)d_in[3];
    const float* Wattn = (const float*)d_in[4];
    const float* b     = (const float*)d_in[5];
    float* out = (float*)d_out;

    k_init<<<(NN * HH + 255) / 256, 256>>>(A);
    k_aw<<<dim3(GG / 128, (NN * LL) / 64), 128>>>(A, Wattn);

    for (int t = 0; t < TT; t++) {
        k_attn<<<NN, 256>>>(A);
        k_gemm<<<dim3(GG / 128, NN / 64), 128>>>(x, Wx, Wh, b, t);
        k_point<<<(NN * HH) / 256, 256>>>(out, t);
    }
}

// round 9
// speedup vs baseline: 2.9882x; 2.9882x over previous
#include <cuda_runtime.h>
#include <cuda_bf16.h>
#include <math.h>
#include <stdint.h>

// Problem constants
#define NN 256
#define TT 128
#define DD 512
#define HH 1024
#define GG 4096   // 4*H
#define LL 16
#define KX 2560   // D + H + H  (x | h | attn)

// ---------------- helpers ----------------
__device__ __forceinline__ uint32_t smem_u32(const void* p) {
    uint32_t a;
    asm("{ .reg .u64 t; cvta.to.shared.u64 t, %1; cvt.u32.u64 %0, t; }" : "=r"(a) : "l"(p));
    return a;
}

__device__ __forceinline__ void cp16(uint32_t dst, const void* src) {
    asm volatile("cp.async.cg.shared.global [%0], [%1], 16;" :: "r"(dst), "l"(src));
}
#define CP_COMMIT() asm volatile("cp.async.commit_group;" ::: "memory")
#define CP_WAIT0()  asm volatile("cp.async.wait_group 0;" ::: "memory")
#define CP_WAIT1()  asm volatile("cp.async.wait_group 1;" ::: "memory")

// m16n8k16 row.col bf16 -> fp32 accumulate (plain sm_80+ PTX; no 'a' features)
__device__ __forceinline__ void mma_bf16(float d[4], const uint32_t a[4], const uint32_t b[2]) {
    asm volatile(
        "mma.sync.aligned.m16n8k16.row.col.f32.bf16.bf16.f32 "
        "{%0,%1,%2,%3}, {%4,%5,%6,%7}, {%8,%9}, {%0,%1,%2,%3};"
        : "+f"(d[0]), "+f"(d[1]), "+f"(d[2]), "+f"(d[3])
        : "r"(a[0]), "r"(a[1]), "r"(a[2]), "r"(a[3]), "r"(b[0]), "r"(b[1]));
}

// ---------------- scratch (device globals) ----------------
__device__ float g_h[NN * HH];          // fp32 h0 (used by k_pa t=-1 only)
__device__ float g_c[NN * HH];
__device__ float g_gates[NN * GG];
__device__ __nv_bfloat16 g_xh[(size_t)NN * TT * DD];
__device__ __nv_bfloat16 g_xl[(size_t)NN * TT * DD];
__device__ __nv_bfloat16 g_hh[NN * HH];
__device__ __nv_bfloat16 g_hl[NN * HH];
__device__ __nv_bfloat16 g_ah[NN * HH];  // attn hi
__device__ __nv_bfloat16 g_al[NN * HH];  // attn lo
__device__ __nv_bfloat16 g_wth[(size_t)GG * KX];  // W^T [j][k], k = x|h|attn
__device__ __nv_bfloat16 g_wtl[(size_t)GG * KX];

// ---------------- one-time: h0 = c0 = mean_l A ----------------
__global__ void k_init(const float* __restrict__ A)
{
    int idx = blockIdx.x * blockDim.x + threadIdx.x;
    if (idx >= NN * HH) return;
    const float4* p = (const float4*)(A + (size_t)idx * LL);
    float4 a0 = p[0], a1 = p[1], a2 = p[2], a3 = p[3];
    float s = a0.x + a0.y + a0.z + a0.w + a1.x + a1.y + a1.z + a1.w
            + a2.x + a2.y + a2.z + a2.w + a3.x + a3.y + a3.z + a3.w;
    s *= (1.0f / LL);
    g_h[idx] = s;
    g_c[idx] = s;
    __nv_bfloat16 hi = __float2bfloat16(s);
    g_hh[idx] = hi;
    g_hl[idx] = __float2bfloat16(s - __bfloat162float(hi));
}

// ---------------- one-time: x -> bf16 hi/lo ----------------
__global__ void k_xcvt(const float* __restrict__ x)
{
    size_t idx = (size_t)blockIdx.x * blockDim.x + threadIdx.x;
    float v = x[idx];
    __nv_bfloat16 hi = __float2bfloat16(v);
    g_xh[idx] = hi;
    g_xl[idx] = __float2bfloat16(v - __bfloat162float(hi));
}

// ---------------- one-time: transpose [Wx;Wh;Wattn] -> Wt[j][k] bf16 hi/lo ----------------
__global__ void k_wcvt(const float* __restrict__ Wx, const float* __restrict__ Wh,
                       const float* __restrict__ Wattn)
{
    __shared__ float tile[32][33];
    int k0 = blockIdx.x * 32;
    int j0 = blockIdx.y * 32;
    int tx = threadIdx.x;
    int ty = threadIdx.y;
#pragma unroll
    for (int i = 0; i < 4; i++) {
        int k = k0 + ty + i * 8;
        float v;
        if (k < DD)            v = Wx[(size_t)k * GG + j0 + tx];
        else if (k < DD + HH)  v = Wh[(size_t)(k - DD) * GG + j0 + tx];
        else                   v = Wattn[(size_t)(k - DD - HH) * GG + j0 + tx];
        tile[ty + i * 8][tx] = v;
    }
    __syncthreads();
#pragma unroll
    for (int i = 0; i < 4; i++) {
        int jj = ty + i * 8;
        float v = tile[tx][jj];
        __nv_bfloat16 hi = __float2bfloat16(v);
        size_t off = (size_t)(j0 + jj) * KX + k0 + tx;
        g_wth[off] = hi;
        g_wtl[off] = __float2bfloat16(v - __bfloat162float(hi));
    }
}

// ---------------- per-step GEMM: gates = [x|h|attn] @ Wt^T + b ----------------
// M=256, N=4096, K=2560. CTA 64x128, 8 warps (2M x 4N) of 32x32 warp tiles.
// bf16 3-term split, fp32 accum, cp.async double-buffered K chunks of 32.
#define NCH 80
#define RSB 80                 // smem row stride bytes (40 bf16, conflict-free)
#define ST_AH 0
#define ST_AL 5120             // 64*80
#define ST_BH 10240
#define ST_BL 20480            // + 128*80
#define STAGE 30720
#define GSMEM (2 * STAGE)

__global__ __launch_bounds__(256) void k_gemm(const float* __restrict__ bias, int t)
{
    extern __shared__ __align__(16) char sm[];
    uint32_t smb = smem_u32(sm);
    int tid  = threadIdx.x;
    int j0 = blockIdx.x * 128;
    int m0 = blockIdx.y * 64;
    int wid = tid >> 5, lane = tid & 31;
    int wm = wid & 1, wn = wid >> 1;
    int g = lane >> 2, tq = lane & 3;

    float acc[2][4][4];
#pragma unroll
    for (int a = 0; a < 2; a++)
#pragma unroll
        for (int b = 0; b < 4; b++)
#pragma unroll
            for (int c = 0; c < 4; c++) acc[a][b][c] = 0.0f;

    auto issue = [&](int ch) {
        int kc = ch * 32;
        uint32_t st = smb + (ch & 1) * STAGE;
#pragma unroll
        for (int i = 0; i < 6; i++) {
            int id = tid + i * 256;
            if (id < 512) {
                int mat = id >> 8;          // 0=hi 1=lo
                int e   = id & 255;
                int row = e >> 2, q = e & 3;
                int k   = kc + q * 8;
                const __nv_bfloat16* src;
                if (k < DD)
                    src = (mat ? g_xl : g_xh) + ((size_t)(m0 + row) * TT + t) * DD + k;
                else if (k < DD + HH)
                    src = (mat ? g_hl : g_hh) + (size_t)(m0 + row) * HH + (k - DD);
                else
                    src = (mat ? g_al : g_ah) + (size_t)(m0 + row) * HH + (k - DD - HH);
                cp16(st + (mat ? ST_AL : ST_AH) + row * RSB + q * 16, src);
            } else {
                int bi  = id - 512;
                int mat = bi >> 9;
                int e   = bi & 511;
                int row = e >> 2, q = e & 3;
                const __nv_bfloat16* src =
                    (mat ? g_wtl : g_wth) + (size_t)(j0 + row) * KX + kc + q * 8;
                cp16(st + (mat ? ST_BL : ST_BH) + row * RSB + q * 16, src);
            }
        }
    };

    issue(0);
    CP_COMMIT();

    for (int ch = 0; ch < NCH; ch++) {
        if (ch + 1 < NCH) {
            issue(ch + 1);
            CP_COMMIT();
            CP_WAIT1();
        } else {
            CP_WAIT0();
        }
        __syncthreads();
        const char* st = sm + (ch & 1) * STAGE;
#pragma unroll
        for (int ko = 0; ko < 32; ko += 16) {
            int c0 = (ko + 2 * tq) * 2;   // byte offset of this thread's k pair
            uint32_t ah[2][4], al[2][4], bh[4][2], bl[4][2];
#pragma unroll
            for (int tm = 0; tm < 2; tm++) {
                int rb = wm * 32 + tm * 16;
                const char* ph = st + ST_AH;
                const char* pl = st + ST_AL;
                ah[tm][0] = *(const uint32_t*)(ph + (rb + g    ) * RSB + c0);
                ah[tm][1] = *(const uint32_t*)(ph + (rb + g + 8) * RSB + c0);
                ah[tm][2] = *(const uint32_t*)(ph + (rb + g    ) * RSB + c0 + 16);
                ah[tm][3] = *(const uint32_t*)(ph + (rb + g + 8) * RSB + c0 + 16);
                al[tm][0] = *(const uint32_t*)(pl + (rb + g    ) * RSB + c0);
                al[tm][1] = *(const uint32_t*)(pl + (rb + g + 8) * RSB + c0);
                al[tm][2] = *(const uint32_t*)(pl + (rb + g    ) * RSB + c0 + 16);
                al[tm][3] = *(const uint32_t*)(pl + (rb + g + 8) * RSB + c0 + 16);
            }
#pragma unroll
            for (int tn = 0; tn < 4; tn++) {
                int nb = wn * 32 + tn * 8;
                const char* ph = st + ST_BH;
                const char* pl = st + ST_BL;
                bh[tn][0] = *(const uint32_t*)(ph + (nb + g) * RSB + c0);
                bh[tn][1] = *(const uint32_t*)(ph + (nb + g) * RSB + c0 + 16);
                bl[tn][0] = *(const uint32_t*)(pl + (nb + g) * RSB + c0);
                bl[tn][1] = *(const uint32_t*)(pl + (nb + g) * RSB + c0 + 16);
            }
#pragma unroll
            for (int tm = 0; tm < 2; tm++)
#pragma unroll
                for (int tn = 0; tn < 4; tn++) {
                    mma_bf16(acc[tm][tn], ah[tm], bh[tn]);  // hi*hi
                    mma_bf16(acc[tm][tn], ah[tm], bl[tn]);  // hi*lo
                    mma_bf16(acc[tm][tn], al[tm], bh[tn]);  // lo*hi
                }
        }
        __syncthreads();
    }

    // epilogue: + bias, write gates
#pragma unroll
    for (int tm = 0; tm < 2; tm++) {
        int r0 = m0 + wm * 32 + tm * 16 + g;
#pragma unroll
        for (int tn = 0; tn < 4; tn++) {
            int j = j0 + wn * 32 + tn * 8 + 2 * tq;
            float2 bb = *(const float2*)&bias[j];
            float2 v0 = {acc[tm][tn][0] + bb.x, acc[tm][tn][1] + bb.y};
            float2 v1 = {acc[tm][tn][2] + bb.x, acc[tm][tn][3] + bb.y};
            *(float2*)&g_gates[(size_t)r0 * GG + j]       = v0;
            *(float2*)&g_gates[(size_t)(r0 + 8) * GG + j] = v1;
        }
    }
}

// ---------------- per-step fused pointwise LSTM + attention ----------------
// t >= 0: consume gates -> h,c,out ; then scores/softmax/attn for next step.
// t == -1: attn from initial g_h only.
__global__ __launch_bounds__(256) void k_pa(const float* __restrict__ A,
                                            float* __restrict__ out, int t)
{
    int n   = blockIdx.x;
    int tid = threadIdx.x;
    __shared__ float sh[HH];
    __shared__ float red[8][16];
    __shared__ float wsm[16];

    if (t >= 0) {
        const float* gb = &g_gates[(size_t)n * GG];
#pragma unroll
        for (int i = 0; i < 4; i++) {
            int p = tid + i * 256;
            float iv = gb[p];
            float fv = gb[HH + p];
            float ov = gb[2 * HH + p];
            float gv = gb[3 * HH + p];
            float c  = g_c[n * HH + p];
            float si = 1.0f / (1.0f + expf(-iv));
            float sf = 1.0f / (1.0f + expf(-fv));
            float so = 1.0f / (1.0f + expf(-ov));
            float tg = tanhf(gv);
            float cn = sf * c + si * tg;
            float hn = so * tanhf(cn);
            g_c[n * HH + p] = cn;
            sh[p] = hn;
            __nv_bfloat16 hi = __float2bfloat16(hn);
            g_hh[n * HH + p] = hi;
            g_hl[n * HH + p] = __float2bfloat16(hn - __bfloat162float(hi));
            out[((size_t)n * TT + t) * HH + p] = hn;
        }
    } else {
#pragma unroll
        for (int i = 0; i < 4; i++) {
            int p = tid + i * 256;
            sh[p] = g_h[n * HH + p];
        }
    }
    __syncthreads();

    // scores_l = sum_h A[n,h,l] * h[h]
    float acc[16];
#pragma unroll
    for (int l = 0; l < 16; l++) acc[l] = 0.0f;
#pragma unroll
    for (int i = 0; i < 4; i++) {
        int hh = tid + i * 256;
        float hv = sh[hh];
        const float4* ap = (const float4*)&A[((size_t)n * HH + hh) * LL];
        float4 a0 = ap[0], a1 = ap[1], a2 = ap[2], a3 = ap[3];
        acc[0]  += a0.x * hv; acc[1]  += a0.y * hv; acc[2]  += a0.z * hv; acc[3]  += a0.w * hv;
        acc[4]  += a1.x * hv; acc[5]  += a1.y * hv; acc[6]  += a1.z * hv; acc[7]  += a1.w * hv;
        acc[8]  += a2.x * hv; acc[9]  += a2.y * hv; acc[10] += a2.z * hv; acc[11] += a2.w * hv;
        acc[12] += a3.x * hv; acc[13] += a3.y * hv; acc[14] += a3.z * hv; acc[15] += a3.w * hv;
    }
#pragma unroll
    for (int off = 16; off; off >>= 1)
#pragma unroll
        for (int l = 0; l < 16; l++)
            acc[l] += __shfl_xor_sync(0xffffffff, acc[l], off);

    int wid = tid >> 5, lane = tid & 31;
    if (lane < 16) red[wid][lane] = acc[lane];
    __syncthreads();

    if (tid == 0) {
        float s[16];
#pragma unroll
        for (int l = 0; l < 16; l++) {
            float v = 0.0f;
#pragma unroll
            for (int wq = 0; wq < 8; wq++) v += red[wq][l];
            s[l] = v * 0.03125f;   // 1/sqrt(1024)
        }
        float mx = s[0];
#pragma unroll
        for (int l = 1; l < 16; l++) mx = fmaxf(mx, s[l]);
        float e[16], den = 0.0f;
#pragma unroll
        for (int l = 0; l < 16; l++) { e[l] = expf(s[l] - mx); den += e[l]; }
        float inv = 1.0f / den;
#pragma unroll
        for (int l = 0; l < 16; l++) wsm[l] = e[l] * inv;
    }
    __syncthreads();

    // attn[h] = sum_l A[n,h,l] * w[l]  -> bf16 hi/lo
    float w0x = wsm[0],  w0y = wsm[1],  w0z = wsm[2],  w0w = wsm[3];
    float w1x = wsm[4],  w1y = wsm[5],  w1z = wsm[6],  w1w = wsm[7];
    float w2x = wsm[8],  w2y = wsm[9],  w2z = wsm[10], w2w = wsm[11];
    float w3x = wsm[12], w3y = wsm[13], w3z = wsm[14], w3w = wsm[15];
#pragma unroll
    for (int i = 0; i < 4; i++) {
        int hh = tid + i * 256;
        const float4* ap = (const float4*)&A[((size_t)n * HH + hh) * LL];
        float4 a0 = ap[0], a1 = ap[1], a2 = ap[2], a3 = ap[3];
        float s = a0.x * w0x + a0.y * w0y + a0.z * w0z + a0.w * w0w
                + a1.x * w1x + a1.y * w1y + a1.z * w1z + a1.w * w1w
                + a2.x * w2x + a2.y * w2y + a2.z * w2z + a2.w * w2w
                + a3.x * w3x + a3.y * w3y + a3.z * w3z + a3.w * w3w;
        __nv_bfloat16 hi = __float2bfloat16(s);
        g_ah[n * HH + hh] = hi;
        g_al[n * HH + hh] = __float2bfloat16(s - __bfloat162float(hi));
    }
}

// ---------------- launch ----------------
extern "C" void kernel_launch(void* const* d_in, const int* in_sizes, int n_in,
                              void* d_out, int out_size)
{
    const float* x     = (const float*)d_in[0];
    const float* A     = (const float*)d_in[1];
    const float* Wx    = (const float*)d_in[2];
    const float* Wh    = (const float*)d_in[3];
    const float* Wattn = (const float*)d_in[4];
    const float* b     = (const float*)d_in[5];
    float* out = (float*)d_out;

    static int smem_set = 0;
    if (!smem_set) {
        cudaFuncSetAttribute(k_gemm, cudaFuncAttributeMaxDynamicSharedMemorySize, GSMEM);
        smem_set = 1;
    }

    k_init<<<(NN * HH + 255) / 256, 256>>>(A);
    k_xcvt<<<(NN * TT * DD) / 256, 256>>>(x);
    k_wcvt<<<dim3(KX / 32, GG / 32), dim3(32, 8)>>>(Wx, Wh, Wattn);
    k_pa<<<NN, 256>>>(A, out, -1);   // attn from h0

    for (int t = 0; t < TT; t++) {
        k_gemm<<<dim3(GG / 128, NN / 64), 256, GSMEM>>>(b, t);
        k_pa<<<NN, 256>>>(A, out, t);
    }
}

// round 10
// speedup vs baseline: 3.5350x; 1.1830x over previous
#include <cuda_runtime.h>
#include <cuda_bf16.h>
#include <math.h>
#include <stdint.h>

// Problem constants
#define NN 256
#define TT 128
#define DD 512
#define HH 1024
#define GG 4096   // 4*H
#define LL 16
#define KX 2560   // D + H + H  (x | h | attn)

// ---------------- helpers ----------------
__device__ __forceinline__ uint32_t smem_u32(const void* p) {
    uint32_t a;
    asm("{ .reg .u64 t; cvta.to.shared.u64 t, %1; cvt.u32.u64 %0, t; }" : "=r"(a) : "l"(p));
    return a;
}

__device__ __forceinline__ void cp16(uint32_t dst, const void* src) {
    asm volatile("cp.async.cg.shared.global [%0], [%1], 16;" :: "r"(dst), "l"(src));
}
#define CP_COMMIT() asm volatile("cp.async.commit_group;" ::: "memory")
#define CP_WAIT0()  asm volatile("cp.async.wait_group 0;" ::: "memory")
#define CP_WAIT1()  asm volatile("cp.async.wait_group 1;" ::: "memory")

// m16n8k16 row.col bf16 -> fp32 accumulate
__device__ __forceinline__ void mma_bf16(float d[4], const uint32_t a[4], const uint32_t b[2]) {
    asm volatile(
        "mma.sync.aligned.m16n8k16.row.col.f32.bf16.bf16.f32 "
        "{%0,%1,%2,%3}, {%4,%5,%6,%7}, {%8,%9}, {%0,%1,%2,%3};"
        : "+f"(d[0]), "+f"(d[1]), "+f"(d[2]), "+f"(d[3])
        : "r"(a[0]), "r"(a[1]), "r"(a[2]), "r"(a[3]), "r"(b[0]), "r"(b[1]));
}

__device__ __forceinline__ void ldmx4(uint32_t r[4], uint32_t addr) {
    asm volatile("ldmatrix.sync.aligned.m8n8.x4.shared.b16 {%0,%1,%2,%3}, [%4];"
                 : "=r"(r[0]), "=r"(r[1]), "=r"(r[2]), "=r"(r[3]) : "r"(addr));
}

// ---------------- scratch (device globals) ----------------
__device__ float g_h[NN * HH];
__device__ float g_c[NN * HH];
__device__ float g_gates[NN * GG];
__device__ __nv_bfloat16 g_xh[(size_t)NN * TT * DD];
__device__ __nv_bfloat16 g_xl[(size_t)NN * TT * DD];
__device__ __nv_bfloat16 g_hh[NN * HH];
__device__ __nv_bfloat16 g_hl[NN * HH];
__device__ __nv_bfloat16 g_ah[NN * HH];
__device__ __nv_bfloat16 g_al[NN * HH];
__device__ __nv_bfloat16 g_wth[(size_t)GG * KX];  // W^T [j][k], k = x|h|attn
__device__ __nv_bfloat16 g_wtl[(size_t)GG * KX];

// ---------------- one-time: h0 = c0 = mean_l A ----------------
__global__ void k_init(const float* __restrict__ A)
{
    int idx = blockIdx.x * blockDim.x + threadIdx.x;
    if (idx >= NN * HH) return;
    const float4* p = (const float4*)(A + (size_t)idx * LL);
    float4 a0 = p[0], a1 = p[1], a2 = p[2], a3 = p[3];
    float s = a0.x + a0.y + a0.z + a0.w + a1.x + a1.y + a1.z + a1.w
            + a2.x + a2.y + a2.z + a2.w + a3.x + a3.y + a3.z + a3.w;
    s *= (1.0f / LL);
    g_h[idx] = s;
    g_c[idx] = s;
    __nv_bfloat16 hi = __float2bfloat16(s);
    g_hh[idx] = hi;
    g_hl[idx] = __float2bfloat16(s - __bfloat162float(hi));
}

// ---------------- one-time: x -> bf16 hi/lo ----------------
__global__ void k_xcvt(const float* __restrict__ x)
{
    size_t idx = (size_t)blockIdx.x * blockDim.x + threadIdx.x;
    float v = x[idx];
    __nv_bfloat16 hi = __float2bfloat16(v);
    g_xh[idx] = hi;
    g_xl[idx] = __float2bfloat16(v - __bfloat162float(hi));
}

// ---------------- one-time: transpose [Wx;Wh;Wattn] -> Wt[j][k] bf16 hi/lo ----------------
__global__ void k_wcvt(const float* __restrict__ Wx, const float* __restrict__ Wh,
                       const float* __restrict__ Wattn)
{
    __shared__ float tile[32][33];
    int k0 = blockIdx.x * 32;
    int j0 = blockIdx.y * 32;
    int tx = threadIdx.x;
    int ty = threadIdx.y;
#pragma unroll
    for (int i = 0; i < 4; i++) {
        int k = k0 + ty + i * 8;
        float v;
        if (k < DD)            v = Wx[(size_t)k * GG + j0 + tx];
        else if (k < DD + HH)  v = Wh[(size_t)(k - DD) * GG + j0 + tx];
        else                   v = Wattn[(size_t)(k - DD - HH) * GG + j0 + tx];
        tile[ty + i * 8][tx] = v;
    }
    __syncthreads();
#pragma unroll
    for (int i = 0; i < 4; i++) {
        int jj = ty + i * 8;
        float v = tile[tx][jj];
        __nv_bfloat16 hi = __float2bfloat16(v);
        size_t off = (size_t)(j0 + jj) * KX + k0 + tx;
        g_wth[off] = hi;
        g_wtl[off] = __float2bfloat16(v - __bfloat162float(hi));
    }
}

// ---------------- per-step GEMM: gates = [x|h|attn] @ Wt^T + b ----------------
// M=256, N=4096, K=2560. CTA 64x128, 8 warps (2M x 4N), warp tile 32x32.
// 3-term bf16 split, K chunks of 64, cp.async double-buffer, ldmatrix fragments.
#define NCH 40
#define RSB 144                // padded row stride bytes (128 data + 16 pad) — conflict-free ldmatrix
#define ST_AH 0
#define ST_AL 9216             // 64*144
#define ST_BH 18432
#define ST_BL 36864            // 18432 + 128*144
#define STAGE 55296
#define GSMEM (2 * STAGE)

__global__ __launch_bounds__(256) void k_gemm(const float* __restrict__ bias, int t)
{
    extern __shared__ __align__(16) char sm[];
    uint32_t smb = smem_u32(sm);
    int tid  = threadIdx.x;
    int j0 = blockIdx.x * 128;
    int m0 = blockIdx.y * 64;
    int wid = tid >> 5, lane = tid & 31;
    int wm = wid & 1, wn = wid >> 1;
    int g = lane >> 2, tq = lane & 3;
    int r8 = lane & 7, quad = lane >> 3;

    // ldmatrix per-lane row offsets (within a tile, before ko column shift)
    // A (m8k8 x4): quad0: m+r,k0  quad1: m+8+r,k0  quad2: m+r,k8  quad3: m+8+r,k8
    uint32_t a_loff = (uint32_t)(((quad & 1) * 8 + r8) * RSB + (quad >> 1) * 16);
    // B (n8k8 x4): quad0: n+r,k0  quad1: n+r,k8  quad2: n+8+r,k0  quad3: n+8+r,k8
    uint32_t b_loff = (uint32_t)(((quad >> 1) * 8 + r8) * RSB + (quad & 1) * 16);

    float acc[2][4][4];
#pragma unroll
    for (int a = 0; a < 2; a++)
#pragma unroll
        for (int b = 0; b < 4; b++)
#pragma unroll
            for (int c = 0; c < 4; c++) acc[a][b][c] = 0.0f;

    auto issue = [&](int ch) {
        int kc = ch * 64;
        uint32_t st = smb + (ch & 1) * STAGE;
#pragma unroll
        for (int i = 0; i < 12; i++) {
            int id = tid + i * 256;     // 0..3071
            if (id < 1024) {            // A: 2 mats x 64 rows x 8 cp16
                int mat = id >> 9;
                int e   = id & 511;
                int row = e >> 3, q = e & 7;
                int k   = kc + q * 8;
                const __nv_bfloat16* src;
                if (k < DD)
                    src = (mat ? g_xl : g_xh) + ((size_t)(m0 + row) * TT + t) * DD + k;
                else if (k < DD + HH)
                    src = (mat ? g_hl : g_hh) + (size_t)(m0 + row) * HH + (k - DD);
                else
                    src = (mat ? g_al : g_ah) + (size_t)(m0 + row) * HH + (k - DD - HH);
                cp16(st + (mat ? ST_AL : ST_AH) + row * RSB + q * 16, src);
            } else {                    // B: 2 mats x 128 rows x 8 cp16
                int bi  = id - 1024;
                int mat = bi >> 10;
                int e   = bi & 1023;
                int row = e >> 3, q = e & 7;
                const __nv_bfloat16* src =
                    (mat ? g_wtl : g_wth) + (size_t)(j0 + row) * KX + kc + q * 8;
                cp16(st + (mat ? ST_BL : ST_BH) + row * RSB + q * 16, src);
            }
        }
    };

    issue(0);
    CP_COMMIT();

    uint32_t a_base = (uint32_t)(wm * 32) * RSB + a_loff;
    uint32_t b_base = (uint32_t)(wn * 32) * RSB + b_loff;

    for (int ch = 0; ch < NCH; ch++) {
        if (ch + 1 < NCH) {
            issue(ch + 1);
            CP_COMMIT();
            CP_WAIT1();
        } else {
            CP_WAIT0();
        }
        __syncthreads();
        uint32_t st = smb + (ch & 1) * STAGE;
#pragma unroll
        for (int ko = 0; ko < 64; ko += 16) {
            uint32_t kb = (uint32_t)(ko * 2);
            uint32_t ah[2][4], al[2][4], bf[4][2], bl[4][2];
#pragma unroll
            for (int tm = 0; tm < 2; tm++) {
                ldmx4(ah[tm], st + ST_AH + a_base + (uint32_t)(tm * 16) * RSB + kb);
                ldmx4(al[tm], st + ST_AL + a_base + (uint32_t)(tm * 16) * RSB + kb);
            }
#pragma unroll
            for (int pr = 0; pr < 2; pr++) {
                uint32_t rh[4], rl[4];
                ldmx4(rh, st + ST_BH + b_base + (uint32_t)(pr * 16) * RSB + kb);
                ldmx4(rl, st + ST_BL + b_base + (uint32_t)(pr * 16) * RSB + kb);
                bf[pr * 2][0] = rh[0]; bf[pr * 2][1] = rh[1];
                bf[pr * 2 + 1][0] = rh[2]; bf[pr * 2 + 1][1] = rh[3];
                bl[pr * 2][0] = rl[0]; bl[pr * 2][1] = rl[1];
                bl[pr * 2 + 1][0] = rl[2]; bl[pr * 2 + 1][1] = rl[3];
            }
#pragma unroll
            for (int tm = 0; tm < 2; tm++)
#pragma unroll
                for (int tn = 0; tn < 4; tn++) {
                    mma_bf16(acc[tm][tn], ah[tm], bf[tn]);  // hi*hi
                    mma_bf16(acc[tm][tn], ah[tm], bl[tn]);  // hi*lo
                    mma_bf16(acc[tm][tn], al[tm], bf[tn]);  // lo*hi
                }
        }
        __syncthreads();
    }

    // epilogue: + bias, write gates
#pragma unroll
    for (int tm = 0; tm < 2; tm++) {
        int r0 = m0 + wm * 32 + tm * 16 + g;
#pragma unroll
        for (int tn = 0; tn < 4; tn++) {
            int j = j0 + wn * 32 + tn * 8 + 2 * tq;
            float2 bb = *(const float2*)&bias[j];
            float2 v0 = {acc[tm][tn][0] + bb.x, acc[tm][tn][1] + bb.y};
            float2 v1 = {acc[tm][tn][2] + bb.x, acc[tm][tn][3] + bb.y};
            *(float2*)&g_gates[(size_t)r0 * GG + j]       = v0;
            *(float2*)&g_gates[(size_t)(r0 + 8) * GG + j] = v1;
        }
    }
}

// ---------------- per-step fused pointwise LSTM + attention ----------------
// 1024 threads/block, one h-element per thread; A row cached in registers
// across both the scores pass and the attn pass (halves A traffic).
__global__ __launch_bounds__(1024) void k_pa(const float* __restrict__ A,
                                             float* __restrict__ out, int t)
{
    int n   = blockIdx.x;
    int tid = threadIdx.x;          // == h index
    __shared__ float red[32][16];
    __shared__ float scr[16];
    __shared__ float wsm[16];

    float hv;
    if (t >= 0) {
        const float* gb = &g_gates[(size_t)n * GG];
        float iv = gb[tid];
        float fv = gb[HH + tid];
        float ov = gb[2 * HH + tid];
        float gv = gb[3 * HH + tid];
        float c  = g_c[n * HH + tid];
        float si = 1.0f / (1.0f + expf(-iv));
        float sf = 1.0f / (1.0f + expf(-fv));
        float so = 1.0f / (1.0f + expf(-ov));
        float tg = tanhf(gv);
        float cn = sf * c + si * tg;
        hv = so * tanhf(cn);
        g_c[n * HH + tid] = cn;
        __nv_bfloat16 hi = __float2bfloat16(hv);
        g_hh[n * HH + tid] = hi;
        g_hl[n * HH + tid] = __float2bfloat16(hv - __bfloat162float(hi));
        out[((size_t)n * TT + t) * HH + tid] = hv;
    } else {
        hv = g_h[n * HH + tid];
    }

    // A row cached in registers
    const float4* ap = (const float4*)&A[((size_t)n * HH + tid) * LL];
    float4 a0 = ap[0], a1 = ap[1], a2 = ap[2], a3 = ap[3];

    // scores_l = sum_h A[n,h,l] * h[h]
    float acc[16];
    acc[0]  = a0.x * hv; acc[1]  = a0.y * hv; acc[2]  = a0.z * hv; acc[3]  = a0.w * hv;
    acc[4]  = a1.x * hv; acc[5]  = a1.y * hv; acc[6]  = a1.z * hv; acc[7]  = a1.w * hv;
    acc[8]  = a2.x * hv; acc[9]  = a2.y * hv; acc[10] = a2.z * hv; acc[11] = a2.w * hv;
    acc[12] = a3.x * hv; acc[13] = a3.y * hv; acc[14] = a3.z * hv; acc[15] = a3.w * hv;
#pragma unroll
    for (int off = 16; off; off >>= 1)
#pragma unroll
        for (int l = 0; l < 16; l++)
            acc[l] += __shfl_xor_sync(0xffffffff, acc[l], off);

    int wid = tid >> 5, lane = tid & 31;
    if (lane < 16) red[wid][lane] = acc[lane];
    __syncthreads();

    if (tid < 16) {
        float v = 0.0f;
#pragma unroll
        for (int wq = 0; wq < 32; wq++) v += red[wq][tid];
        scr[tid] = v * 0.03125f;   // 1/sqrt(1024)
    }
    __syncthreads();
    if (tid == 0) {
        float mx = scr[0];
#pragma unroll
        for (int l = 1; l < 16; l++) mx = fmaxf(mx, scr[l]);
        float e[16], den = 0.0f;
#pragma unroll
        for (int l = 0; l < 16; l++) { e[l] = expf(scr[l] - mx); den += e[l]; }
        float inv = 1.0f / den;
#pragma unroll
        for (int l = 0; l < 16; l++) wsm[l] = e[l] * inv;
    }
    __syncthreads();

    // attn[h] = sum_l A[n,h,l] * w[l] from cached registers
    float s = a0.x * wsm[0]  + a0.y * wsm[1]  + a0.z * wsm[2]  + a0.w * wsm[3]
            + a1.x * wsm[4]  + a1.y * wsm[5]  + a1.z * wsm[6]  + a1.w * wsm[7]
            + a2.x * wsm[8]  + a2.y * wsm[9]  + a2.z * wsm[10] + a2.w * wsm[11]
            + a3.x * wsm[12] + a3.y * wsm[13] + a3.z * wsm[14] + a3.w * wsm[15];
    __nv_bfloat16 hi = __float2bfloat16(s);
    g_ah[n * HH + tid] = hi;
    g_al[n * HH + tid] = __float2bfloat16(s - __bfloat162float(hi));
}

// ---------------- launch ----------------
extern "C" void kernel_launch(void* const* d_in, const int* in_sizes, int n_in,
                              void* d_out, int out_size)
{
    const float* x     = (const float*)d_in[0];
    const float* A     = (const float*)d_in[1];
    const float* Wx    = (const float*)d_in[2];
    const float* Wh    = (const float*)d_in[3];
    const float* Wattn = (const float*)d_in[4];
    const float* b     = (const float*)d_in[5];
    float* out = (float*)d_out;

    static int smem_set = 0;
    if (!smem_set) {
        cudaFuncSetAttribute(k_gemm, cudaFuncAttributeMaxDynamicSharedMemorySize, GSMEM);
        smem_set = 1;
    }

    k_init<<<(NN * HH + 255) / 256, 256>>>(A);
    k_xcvt<<<(NN * TT * DD) / 256, 256>>>(x);
    k_wcvt<<<dim3(KX / 32, GG / 32), dim3(32, 8)>>>(Wx, Wh, Wattn);
    k_pa<<<NN, 1024>>>(A, out, -1);   // attn from h0

    for (int t = 0; t < TT; t++) {
        k_gemm<<<dim3(GG / 128, NN / 64), 256, GSMEM>>>(b, t);
        k_pa<<<NN, 1024>>>(A, out, t);
    }
}

// round 15
// speedup vs baseline: 3.7536x; 1.0618x over previous
#include <cuda_runtime.h>
#include <cuda_bf16.h>
#include <math.h>
#include <stdint.h>

// Problem constants
#define NN 256
#define TT 128
#define DD 512
#define HH 1024
#define GG 4096   // 4*H
#define LL 16
#define KX 1536   // D + H  (x | h)
#define KA 1024   // K for AW precompute GEMM

// ---------------- helpers ----------------
__device__ __forceinline__ uint32_t smem_u32(const void* p) {
    uint32_t a;
    asm("{ .reg .u64 t; cvta.to.shared.u64 t, %1; cvt.u32.u64 %0, t; }" : "=r"(a) : "l"(p));
    return a;
}

__device__ __forceinline__ void cp16(uint32_t dst, const void* src) {
    asm volatile("cp.async.cg.shared.global [%0], [%1], 16;" :: "r"(dst), "l"(src));
}
#define CP_COMMIT() asm volatile("cp.async.commit_group;" ::: "memory")
#define CP_WAIT0()  asm volatile("cp.async.wait_group 0;" ::: "memory")
#define CP_WAIT1()  asm volatile("cp.async.wait_group 1;" ::: "memory")
#define CP_WAIT2()  asm volatile("cp.async.wait_group 2;" ::: "memory")

// m16n8k16 row.col bf16 -> fp32 accumulate
__device__ __forceinline__ void mma_bf16(float d[4], const uint32_t a[4], const uint32_t b[2]) {
    asm volatile(
        "mma.sync.aligned.m16n8k16.row.col.f32.bf16.bf16.f32 "
        "{%0,%1,%2,%3}, {%4,%5,%6,%7}, {%8,%9}, {%0,%1,%2,%3};"
        : "+f"(d[0]), "+f"(d[1]), "+f"(d[2]), "+f"(d[3])
        : "r"(a[0]), "r"(a[1]), "r"(a[2]), "r"(a[3]), "r"(b[0]), "r"(b[1]));
}

__device__ __forceinline__ void ldmx4(uint32_t r[4], uint32_t addr) {
    asm volatile("ldmatrix.sync.aligned.m8n8.x4.shared.b16 {%0,%1,%2,%3}, [%4];"
                 : "=r"(r[0]), "=r"(r[1]), "=r"(r[2]), "=r"(r[3]) : "r"(addr));
}

// ---------------- scratch (device globals) ----------------
__device__ float g_h[NN * HH];
__device__ float g_c[NN * HH];
__device__ float g_w[NN * LL];
__device__ float g_gates[NN * GG];
__device__ float g_AW[(size_t)NN * LL * GG];          // 67 MB: AW[(n*16+l)][j]
__device__ __nv_bfloat16 g_xh[(size_t)NN * TT * DD];
__device__ __nv_bfloat16 g_xl[(size_t)NN * TT * DD];
__device__ __nv_bfloat16 g_hh[NN * HH];
__device__ __nv_bfloat16 g_hl[NN * HH];
__device__ __nv_bfloat16 g_wth[(size_t)GG * KX];      // [Wx;Wh]^T [j][k]
__device__ __nv_bfloat16 g_wtl[(size_t)GG * KX];
__device__ __nv_bfloat16 g_wah[(size_t)GG * KA];      // Wattn^T [j][h]
__device__ __nv_bfloat16 g_wal[(size_t)GG * KA];
__device__ __nv_bfloat16 g_ath[(size_t)NN * LL * KA]; // At[(n*16+l)][h]
__device__ __nv_bfloat16 g_atl[(size_t)NN * LL * KA];

// ---------------- one-time: h0 = c0 = mean_l A ----------------
__global__ void k_init(const float* __restrict__ A)
{
    int idx = blockIdx.x * blockDim.x + threadIdx.x;
    if (idx >= NN * HH) return;
    const float4* p = (const float4*)(A + (size_t)idx * LL);
    float4 a0 = p[0], a1 = p[1], a2 = p[2], a3 = p[3];
    float s = a0.x + a0.y + a0.z + a0.w + a1.x + a1.y + a1.z + a1.w
            + a2.x + a2.y + a2.z + a2.w + a3.x + a3.y + a3.z + a3.w;
    s *= (1.0f / LL);
    g_h[idx] = s;
    g_c[idx] = s;
    __nv_bfloat16 hi = __float2bfloat16(s);
    g_hh[idx] = hi;
    g_hl[idx] = __float2bfloat16(s - __bfloat162float(hi));
}

// ---------------- one-time: x -> bf16 hi/lo ----------------
__global__ void k_xcvt(const float* __restrict__ x)
{
    size_t idx = (size_t)blockIdx.x * blockDim.x + threadIdx.x;
    float v = x[idx];
    __nv_bfloat16 hi = __float2bfloat16(v);
    g_xh[idx] = hi;
    g_xl[idx] = __float2bfloat16(v - __bfloat162float(hi));
}

// ---------------- one-time: transpose weights -> bf16 hi/lo ----------------
// k in [0,1536): [Wx;Wh] -> g_wth/g_wtl[j][k]; k in [1536,2560): Wattn -> g_wah/g_wal[j][k-1536]
__global__ void k_wcvt(const float* __restrict__ Wx, const float* __restrict__ Wh,
                       const float* __restrict__ Wattn)
{
    __shared__ float tile[32][33];
    int k0 = blockIdx.x * 32;
    int j0 = blockIdx.y * 32;
    int tx = threadIdx.x;
    int ty = threadIdx.y;
#pragma unroll
    for (int i = 0; i < 4; i++) {
        int k = k0 + ty + i * 8;
        float v;
        if (k < DD)            v = Wx[(size_t)k * GG + j0 + tx];
        else if (k < DD + HH)  v = Wh[(size_t)(k - DD) * GG + j0 + tx];
        else                   v = Wattn[(size_t)(k - DD - HH) * GG + j0 + tx];
        tile[ty + i * 8][tx] = v;
    }
    __syncthreads();
#pragma unroll
    for (int i = 0; i < 4; i++) {
        int jj = ty + i * 8;
        float v = tile[tx][jj];
        __nv_bfloat16 hi = __float2bfloat16(v);
        __nv_bfloat16 lo = __float2bfloat16(v - __bfloat162float(hi));
        int k = k0 + tx;
        if (k < KX) {
            size_t off = (size_t)(j0 + jj) * KX + k;
            g_wth[off] = hi;
            g_wtl[off] = lo;
        } else {
            size_t off = (size_t)(j0 + jj) * KA + (k - KX);
            g_wah[off] = hi;
            g_wal[off] = lo;
        }
    }
}

// ---------------- one-time: A[n][h][l] -> At[(n*16+l)][h] bf16 hi/lo ----------------
__global__ void k_acvt(const float* __restrict__ A)
{
    int n = blockIdx.x;
    int tid = threadIdx.x;   // 256
    __shared__ float sl[16][256];
#pragma unroll
    for (int c = 0; c < 4; c++) {
        int h = c * 256 + tid;
        const float4* ap = (const float4*)&A[((size_t)n * HH + h) * LL];
        float4 a0 = ap[0], a1 = ap[1], a2 = ap[2], a3 = ap[3];
        sl[0][tid]  = a0.x; sl[1][tid]  = a0.y; sl[2][tid]  = a0.z; sl[3][tid]  = a0.w;
        sl[4][tid]  = a1.x; sl[5][tid]  = a1.y; sl[6][tid]  = a1.z; sl[7][tid]  = a1.w;
        sl[8][tid]  = a2.x; sl[9][tid]  = a2.y; sl[10][tid] = a2.z; sl[11][tid] = a2.w;
        sl[12][tid] = a3.x; sl[13][tid] = a3.y; sl[14][tid] = a3.z; sl[15][tid] = a3.w;
        __syncthreads();
#pragma unroll
        for (int l = 0; l < 16; l++) {
            float v = sl[l][tid];
            __nv_bfloat16 hi = __float2bfloat16(v);
            size_t off = (size_t)(n * LL + l) * KA + c * 256 + tid;
            g_ath[off] = hi;
            g_atl[off] = __float2bfloat16(v - __bfloat162float(hi));
        }
        __syncthreads();
    }
}

// ================= shared GEMM tiling constants =================
#define RSB 144                // padded row stride bytes — conflict-free ldmatrix
#define ST_AH 0
#define ST_AL 9216             // 64*144
#define ST_BH 18432
#define ST_BL 36864
#define STAGE 55296
#define GSMEM (3 * STAGE)      // 3-stage pipeline

// ---------------- one-time GEMM: AW[m][j] = sum_h At[m][h] * WaT[j][h] ----------------
// M=4096 (tile 64), N=4096 (tile 128), K=1024 (16 chunks of 64). 3-term bf16 split.
__global__ __launch_bounds__(256) void k_aw(void)
{
    extern __shared__ __align__(16) char sm[];
    uint32_t smb = smem_u32(sm);
    int tid  = threadIdx.x;
    int j0 = blockIdx.x * 128;
    int m0 = blockIdx.y * 64;
    int wid = tid >> 5, lane = tid & 31;
    int wm = wid & 1, wn = wid >> 1;
    int g = lane >> 2, tq = lane & 3;
    int r8 = lane & 7, quad = lane >> 3;
    uint32_t a_loff = (uint32_t)(((quad & 1) * 8 + r8) * RSB + (quad >> 1) * 16);
    uint32_t b_loff = (uint32_t)(((quad >> 1) * 8 + r8) * RSB + (quad & 1) * 16);

    float acc[2][4][4];
#pragma unroll
    for (int a = 0; a < 2; a++)
#pragma unroll
        for (int b = 0; b < 4; b++)
#pragma unroll
            for (int c = 0; c < 4; c++) acc[a][b][c] = 0.0f;

    const int NCHA = KA / 64;   // 16

    auto issue = [&](int ch) {
        int kc = ch * 64;
        uint32_t st = smb + (ch % 3) * STAGE;
#pragma unroll
        for (int i = 0; i < 12; i++) {
            int id = tid + i * 256;
            if (id < 1024) {
                int mat = id >> 9;
                int e   = id & 511;
                int row = e >> 3, q = e & 7;
                const __nv_bfloat16* src =
                    (mat ? g_atl : g_ath) + (size_t)(m0 + row) * KA + kc + q * 8;
                cp16(st + (mat ? ST_AL : ST_AH) + row * RSB + q * 16, src);
            } else {
                int bi  = id - 1024;
                int mat = bi >> 10;
                int e   = bi & 1023;
                int row = e >> 3, q = e & 7;
                const __nv_bfloat16* src =
                    (mat ? g_wal : g_wah) + (size_t)(j0 + row) * KA + kc + q * 8;
                cp16(st + (mat ? ST_BL : ST_BH) + row * RSB + q * 16, src);
            }
        }
    };

    issue(0); CP_COMMIT();
    issue(1); CP_COMMIT();

    uint32_t a_base = (uint32_t)(wm * 32) * RSB + a_loff;
    uint32_t b_base = (uint32_t)(wn * 32) * RSB + b_loff;

    for (int ch = 0; ch < NCHA; ch++) {
        if (ch + 2 < NCHA) { issue(ch + 2); CP_COMMIT(); CP_WAIT2(); }
        else if (ch + 1 < NCHA) { CP_WAIT1(); }
        else { CP_WAIT0(); }
        __syncthreads();
        uint32_t st = smb + (ch % 3) * STAGE;
#pragma unroll
        for (int ko = 0; ko < 64; ko += 16) {
            uint32_t kb = (uint32_t)(ko * 2);
            uint32_t ah[2][4], al[2][4], bf[4][2], bl[4][2];
#pragma unroll
            for (int tm = 0; tm < 2; tm++) {
                ldmx4(ah[tm], st + ST_AH + a_base + (uint32_t)(tm * 16) * RSB + kb);
                ldmx4(al[tm], st + ST_AL + a_base + (uint32_t)(tm * 16) * RSB + kb);
            }
#pragma unroll
            for (int pr = 0; pr < 2; pr++) {
                uint32_t rh[4], rl[4];
                ldmx4(rh, st + ST_BH + b_base + (uint32_t)(pr * 16) * RSB + kb);
                ldmx4(rl, st + ST_BL + b_base + (uint32_t)(pr * 16) * RSB + kb);
                bf[pr * 2][0] = rh[0]; bf[pr * 2][1] = rh[1];
                bf[pr * 2 + 1][0] = rh[2]; bf[pr * 2 + 1][1] = rh[3];
                bl[pr * 2][0] = rl[0]; bl[pr * 2][1] = rl[1];
                bl[pr * 2 + 1][0] = rl[2]; bl[pr * 2 + 1][1] = rl[3];
            }
#pragma unroll
            for (int tm = 0; tm < 2; tm++)
#pragma unroll
                for (int tn = 0; tn < 4; tn++) {
                    mma_bf16(acc[tm][tn], ah[tm], bf[tn]);
                    mma_bf16(acc[tm][tn], ah[tm], bl[tn]);
                    mma_bf16(acc[tm][tn], al[tm], bf[tn]);
                }
        }
        __syncthreads();
    }

#pragma unroll
    for (int tm = 0; tm < 2; tm++) {
        int r0 = m0 + wm * 32 + tm * 16 + g;
#pragma unroll
        for (int tn = 0; tn < 4; tn++) {
            int j = j0 + wn * 32 + tn * 8 + 2 * tq;
            *(float2*)&g_AW[(size_t)r0 * GG + j]       = make_float2(acc[tm][tn][0], acc[tm][tn][1]);
            *(float2*)&g_AW[(size_t)(r0 + 8) * GG + j] = make_float2(acc[tm][tn][2], acc[tm][tn][3]);
        }
    }
}

// ---------------- per-step GEMM: gates = [x|h] @ Wt^T + b + sum_l w_l*AW ----------------
// M=256, N=4096, K=1536 (24 chunks). CTA 64x128, 8 warps, 3-term bf16 split, 3-stage.
#define NCH 24

__global__ __launch_bounds__(256) void k_gemm(const float* __restrict__ bias, int t)
{
    extern __shared__ __align__(16) char sm[];
    __shared__ float sw[64][16];
    uint32_t smb = smem_u32(sm);
    int tid  = threadIdx.x;
    int j0 = blockIdx.x * 128;
    int m0 = blockIdx.y * 64;
    int wid = tid >> 5, lane = tid & 31;
    int wm = wid & 1, wn = wid >> 1;
    int g = lane >> 2, tq = lane & 3;
    int r8 = lane & 7, quad = lane >> 3;
    uint32_t a_loff = (uint32_t)(((quad & 1) * 8 + r8) * RSB + (quad >> 1) * 16);
    uint32_t b_loff = (uint32_t)(((quad >> 1) * 8 + r8) * RSB + (quad & 1) * 16);

    // preload attention weights for this CTA's 64 rows
    for (int i = tid; i < 64 * 16; i += 256)
        sw[i >> 4][i & 15] = g_w[(m0 + (i >> 4)) * LL + (i & 15)];

    float acc[2][4][4];
#pragma unroll
    for (int a = 0; a < 2; a++)
#pragma unroll
        for (int b = 0; b < 4; b++)
#pragma unroll
            for (int c = 0; c < 4; c++) acc[a][b][c] = 0.0f;

    auto issue = [&](int ch) {
        int kc = ch * 64;
        uint32_t st = smb + (ch % 3) * STAGE;
#pragma unroll
        for (int i = 0; i < 12; i++) {
            int id = tid + i * 256;
            if (id < 1024) {
                int mat = id >> 9;
                int e   = id & 511;
                int row = e >> 3, q = e & 7;
                int k   = kc + q * 8;
                const __nv_bfloat16* src;
                if (k < DD)
                    src = (mat ? g_xl : g_xh) + ((size_t)(m0 + row) * TT + t) * DD + k;
                else
                    src = (mat ? g_hl : g_hh) + (size_t)(m0 + row) * HH + (k - DD);
                cp16(st + (mat ? ST_AL : ST_AH) + row * RSB + q * 16, src);
            } else {
                int bi  = id - 1024;
                int mat = bi >> 10;
                int e   = bi & 1023;
                int row = e >> 3, q = e & 7;
                const __nv_bfloat16* src =
                    (mat ? g_wtl : g_wth) + (size_t)(j0 + row) * KX + kc + q * 8;
                cp16(st + (mat ? ST_BL : ST_BH) + row * RSB + q * 16, src);
            }
        }
    };

    issue(0); CP_COMMIT();
    issue(1); CP_COMMIT();

    uint32_t a_base = (uint32_t)(wm * 32) * RSB + a_loff;
    uint32_t b_base = (uint32_t)(wn * 32) * RSB + b_loff;

    for (int ch = 0; ch < NCH; ch++) {
        if (ch + 2 < NCH) { issue(ch + 2); CP_COMMIT(); CP_WAIT2(); }
        else if (ch + 1 < NCH) { CP_WAIT1(); }
        else { CP_WAIT0(); }
        __syncthreads();
        uint32_t st = smb + (ch % 3) * STAGE;
#pragma unroll
        for (int ko = 0; ko < 64; ko += 16) {
            uint32_t kb = (uint32_t)(ko * 2);
            uint32_t ah[2][4], al[2][4], bf[4][2], bl[4][2];
#pragma unroll
            for (int tm = 0; tm < 2; tm++) {
                ldmx4(ah[tm], st + ST_AH + a_base + (uint32_t)(tm * 16) * RSB + kb);
                ldmx4(al[tm], st + ST_AL + a_base + (uint32_t)(tm * 16) * RSB + kb);
            }
#pragma unroll
            for (int pr = 0; pr < 2; pr++) {
                uint32_t rh[4], rl[4];
                ldmx4(rh, st + ST_BH + b_base + (uint32_t)(pr * 16) * RSB + kb);
                ldmx4(rl, st + ST_BL + b_base + (uint32_t)(pr * 16) * RSB + kb);
                bf[pr * 2][0] = rh[0]; bf[pr * 2][1] = rh[1];
                bf[pr * 2 + 1][0] = rh[2]; bf[pr * 2 + 1][1] = rh[3];
                bl[pr * 2][0] = rl[0]; bl[pr * 2][1] = rl[1];
                bl[pr * 2 + 1][0] = rl[2]; bl[pr * 2 + 1][1] = rl[3];
            }
#pragma unroll
            for (int tm = 0; tm < 2; tm++)
#pragma unroll
                for (int tn = 0; tn < 4; tn++) {
                    mma_bf16(acc[tm][tn], ah[tm], bf[tn]);
                    mma_bf16(acc[tm][tn], ah[tm], bl[tn]);
                    mma_bf16(acc[tm][tn], al[tm], bf[tn]);
                }
        }
        __syncthreads();
    }

    // epilogue: + bias + sum_l w_l * AW[(n,l)][j]; write gates
#pragma unroll
    for (int tm = 0; tm < 2; tm++) {
#pragma unroll
        for (int rr = 0; rr < 2; rr++) {
            int lrow = wm * 32 + tm * 16 + rr * 8 + g;
            int n    = m0 + lrow;
            const float* awb = &g_AW[(size_t)n * LL * GG];
            float2 v[4];
#pragma unroll
            for (int tn = 0; tn < 4; tn++) {
                int j = j0 + wn * 32 + tn * 8 + 2 * tq;
                float2 bb = *(const float2*)&bias[j];
                v[tn] = make_float2(acc[tm][tn][rr * 2 + 0] + bb.x,
                                    acc[tm][tn][rr * 2 + 1] + bb.y);
            }
#pragma unroll
            for (int l = 0; l < 16; l++) {
                float wl = sw[lrow][l];
                const float* awl = awb + (size_t)l * GG;
#pragma unroll
                for (int tn = 0; tn < 4; tn++) {
                    int j = j0 + wn * 32 + tn * 8 + 2 * tq;
                    float2 aw = *(const float2*)&awl[j];
                    v[tn].x += wl * aw.x;
                    v[tn].y += wl * aw.y;
                }
            }
#pragma unroll
            for (int tn = 0; tn < 4; tn++) {
                int j = j0 + wn * 32 + tn * 8 + 2 * tq;
                *(float2*)&g_gates[(size_t)n * GG + j] = v[tn];
            }
        }
    }
}

// ---------------- per-step fused pointwise LSTM + attention weights ----------------
// 1024 threads/block, one h-element per thread. Computes h,c,out then
// scores -> softmax -> g_w (no attn vector needed anymore).
__global__ __launch_bounds__(1024) void k_pa(const float* __restrict__ A,
                                             float* __restrict__ out, int t)
{
    int n   = blockIdx.x;
    int tid = threadIdx.x;          // == h index
    __shared__ float red[32][16];
    __shared__ float scr[16];

    float hv;
    if (t >= 0) {
        const float* gb = &g_gates[(size_t)n * GG];
        float iv = gb[tid];
        float fv = gb[HH + tid];
        float ov = gb[2 * HH + tid];
        float gv = gb[3 * HH + tid];
        float c  = g_c[n * HH + tid];
        float si = 1.0f / (1.0f + __expf(-iv));
        float sf = 1.0f / (1.0f + __expf(-fv));
        float so = 1.0f / (1.0f + __expf(-ov));
        float tg = tanhf(gv);
        float cn = sf * c + si * tg;
        hv = so * tanhf(cn);
        g_c[n * HH + tid] = cn;
        __nv_bfloat16 hi = __float2bfloat16(hv);
        g_hh[n * HH + tid] = hi;
        g_hl[n * HH + tid] = __float2bfloat16(hv - __bfloat162float(hi));
        out[((size_t)n * TT + t) * HH + tid] = hv;
    } else {
        hv = g_h[n * HH + tid];
    }

    // scores_l = sum_h A[n,h,l] * h[h]
    const float4* ap = (const float4*)&A[((size_t)n * HH + tid) * LL];
    float4 a0 = ap[0], a1 = ap[1], a2 = ap[2], a3 = ap[3];
    float acc[16];
    acc[0]  = a0.x * hv; acc[1]  = a0.y * hv; acc[2]  = a0.z * hv; acc[3]  = a0.w * hv;
    acc[4]  = a1.x * hv; acc[5]  = a1.y * hv; acc[6]  = a1.z * hv; acc[7]  = a1.w * hv;
    acc[8]  = a2.x * hv; acc[9]  = a2.y * hv; acc[10] = a2.z * hv; acc[11] = a2.w * hv;
    acc[12] = a3.x * hv; acc[13] = a3.y * hv; acc[14] = a3.z * hv; acc[15] = a3.w * hv;
#pragma unroll
    for (int off = 16; off; off >>= 1)
#pragma unroll
        for (int l = 0; l < 16; l++)
            acc[l] += __shfl_xor_sync(0xffffffff, acc[l], off);

    int wid = tid >> 5, lane = tid & 31;
    if (lane < 16) red[wid][lane] = acc[lane];
    __syncthreads();

    if (tid < 16) {
        float v = 0.0f;
#pragma unroll
        for (int wq = 0; wq < 32; wq++) v += red[wq][tid];
        scr[tid] = v * 0.03125f;   // 1/sqrt(1024)
    }
    __syncthreads();
    if (tid == 0) {
        float mx = scr[0];
#pragma unroll
        for (int l = 1; l < 16; l++) mx = fmaxf(mx, scr[l]);
        float e[16], den = 0.0f;
#pragma unroll
        for (int l = 0; l < 16; l++) { e[l] = __expf(scr[l] - mx); den += e[l]; }
        float inv = 1.0f / den;
#pragma unroll
        for (int l = 0; l < 16; l++) g_w[n * LL + l] = e[l] * inv;
    }
}

// ---------------- launch ----------------
extern "C" void kernel_launch(void* const* d_in, const int* in_sizes, int n_in,
                              void* d_out, int out_size)
{
    const float* x     = (const float*)d_in[0];
    const float* A     = (const float*)d_in[1];
    const float* Wx    = (const float*)d_in[2];
    const float* Wh    = (const float*)d_in[3];
    const float* Wattn = (const float*)d_in[4];
    const float* b     = (const float*)d_in[5];
    float* out = (float*)d_out;

    static int smem_set = 0;
    if (!smem_set) {
        cudaFuncSetAttribute(k_gemm, cudaFuncAttributeMaxDynamicSharedMemorySize, GSMEM);
        cudaFuncSetAttribute(k_aw,   cudaFuncAttributeMaxDynamicSharedMemorySize, GSMEM);
        smem_set = 1;
    }

    k_init<<<(NN * HH + 255) / 256, 256>>>(A);
    k_xcvt<<<(NN * TT * DD) / 256, 256>>>(x);
    k_wcvt<<<dim3((KX + KA) / 32, GG / 32), dim3(32, 8)>>>(Wx, Wh, Wattn);
    k_acvt<<<NN, 256>>>(A);
    k_aw<<<dim3(GG / 128, (NN * LL) / 64), 256, GSMEM>>>();
    k_pa<<<NN, 1024>>>(A, out, -1);   // w from h0

    for (int t = 0; t < TT; t++) {
        k_gemm<<<dim3(GG / 128, NN / 64), 256, GSMEM>>>(b, t);
        k_pa<<<NN, 1024>>>(A, out, t);
    }
}